// round 16
// baseline (speedup 1.0000x reference)
#include <cuda_runtime.h>
#include <cstddef>

#define L_SEQ 512
#define B_SZ  64
#define D_IN  512
#define HALFH 256
#define G4    1024                 // 4*HALF gate rows per direction
#define M_TOT (L_SEQ * B_SZ)      // 32768

#define CL_N  8                   // CTAs per cluster (hidden split)
#define BB_N  8                   // batch rows per CTA
#define JJ_N  32                  // hidden units per CTA
#define WROWS 128                 // 4 gates * JJ_N
#define RS    260                 // padded row stride (floats); 260 % 32 = 4
#define HBUF_FLOATS (BB_N * RS)            // 2080
#define HBUF_BYTES  (HBUF_FLOATS * 4)      // 8320
#define SMEM_BYTES  ((WROWS * RS + 2 * HBUF_FLOATS) * 4)   // 149760

typedef unsigned long long u64;
typedef unsigned int u32;

// ---------------------------------------------------------------------------
// Packed fp32x2 helpers (sm_100+). IEEE fp32 per lane.
// ---------------------------------------------------------------------------
__device__ __forceinline__ u64 f2_dup(float v) {
    u64 r; asm("mov.b64 %0, {%1, %1};" : "=l"(r) : "f"(v)); return r;
}
__device__ __forceinline__ void f2_unpack(u64 p, float& lo, float& hi) {
    asm("mov.b64 {%0, %1}, %2;" : "=f"(lo), "=f"(hi) : "l"(p));
}
__device__ __forceinline__ u64 f2_fma(u64 a, u64 b, u64 c) {
    u64 d; asm("fma.rn.f32x2 %0, %1, %2, %3;" : "=l"(d) : "l"(a), "l"(b), "l"(c));
    return d;
}

// Fast tanh via MUFU: tanh(x) = 1 - 2/(e^{2x}+1). Saturates correctly.
__device__ __forceinline__ float fast_tanh(float x) {
    float e = __expf(2.0f * x);
    return 1.0f - __fdividef(2.0f, e + 1.0f);
}

// DSMEM helpers
__device__ __forceinline__ u32 smem_u32(const void* p) {
    u32 a;
    asm("{ .reg .u64 t; cvta.to.shared.u64 t, %1; cvt.u32.u64 %0, t; }"
        : "=r"(a) : "l"(p));
    return a;
}
__device__ __forceinline__ u32 mapa_u32(u32 a, int rank) {
    u32 r; asm("mapa.shared::cluster.u32 %0, %1, %2;" : "=r"(r) : "r"(a), "r"(rank));
    return r;
}
__device__ __forceinline__ void st_dsmem(u32 addr, float v) {
    asm volatile("st.shared::cluster.f32 [%0], %1;" :: "r"(addr), "f"(v) : "memory");
}
__device__ __forceinline__ void cluster_sync_hw() {
    asm volatile("barrier.cluster.arrive.aligned;" ::: "memory");  // release
    asm volatile("barrier.cluster.wait.aligned;"   ::: "memory");  // acquire
}

// Scratch: xw[dir][g][m] with m = l*B + b   (256 MB, module-static: allowed)
__device__ float g_xw[(size_t)2 * G4 * M_TOT];

// ---------------------------------------------------------------------------
// Kernel 1: xw[dir][g][m] = sum_d W_ih[g][d] * x[m][d] + b_ih[g] + b_hh[g]
// Tiles: 64(g) x 64(m) x 16(k), 256 threads, 4x4 register tile, FFMA2 math.
// (FROZEN -- attribution isolation for the recurrence rewrite)
// ---------------------------------------------------------------------------
__global__ __launch_bounds__(256) void gemm_xw_kernel(
    const float* __restrict__ x,
    const float* __restrict__ Wf, const float* __restrict__ Wb,
    const float* __restrict__ bihf, const float* __restrict__ bhhf,
    const float* __restrict__ bihb, const float* __restrict__ bhhb)
{
    const int dir = blockIdx.z;
    const float* __restrict__ W   = dir ? Wb   : Wf;
    const float* __restrict__ bih = dir ? bihb : bihf;
    const float* __restrict__ bhh = dir ? bhhb : bhhf;

    const int m0 = blockIdx.x * 64;
    const int g0 = blockIdx.y * 64;

    __shared__ float As[16][68];   // As[k][g']
    __shared__ float Bs[16][68];   // Bs[k][m']

    const int tid = threadIdx.x;
    const int tx  = tid & 15;      // m sub-tile
    const int ty  = tid >> 4;      // g sub-tile

    const int lrow = tid >> 2;          // 0..63 (tile row to load)
    const int lc   = (tid & 3) * 4;     // k offset 0,4,8,12

    const float* Arow = W + (size_t)(g0 + lrow) * D_IN + lc;
    const float* Brow = x + (size_t)(m0 + lrow) * D_IN + lc;

    u64 acc2[4][2] = {};

    for (int k0 = 0; k0 < D_IN; k0 += 16) {
        float4 av = *(const float4*)(Arow + k0);
        float4 bv = *(const float4*)(Brow + k0);
        __syncthreads();
        As[lc + 0][lrow] = av.x; As[lc + 1][lrow] = av.y;
        As[lc + 2][lrow] = av.z; As[lc + 3][lrow] = av.w;
        Bs[lc + 0][lrow] = bv.x; Bs[lc + 1][lrow] = bv.y;
        Bs[lc + 2][lrow] = bv.z; Bs[lc + 3][lrow] = bv.w;
        __syncthreads();
#pragma unroll
        for (int kk = 0; kk < 16; kk++) {
            float4     a  = *(const float4*)&As[kk][ty * 4];
            ulonglong2 bp = *(const ulonglong2*)&Bs[kk][tx * 4];
            u64 d0 = f2_dup(a.x), d1 = f2_dup(a.y),
                d2 = f2_dup(a.z), d3 = f2_dup(a.w);
            acc2[0][0] = f2_fma(d0, bp.x, acc2[0][0]);
            acc2[0][1] = f2_fma(d0, bp.y, acc2[0][1]);
            acc2[1][0] = f2_fma(d1, bp.x, acc2[1][0]);
            acc2[1][1] = f2_fma(d1, bp.y, acc2[1][1]);
            acc2[2][0] = f2_fma(d2, bp.x, acc2[2][0]);
            acc2[2][1] = f2_fma(d2, bp.y, acc2[2][1]);
            acc2[3][0] = f2_fma(d3, bp.x, acc2[3][0]);
            acc2[3][1] = f2_fma(d3, bp.y, acc2[3][1]);
        }
    }

#pragma unroll
    for (int i = 0; i < 4; i++) {
        int g = g0 + ty * 4 + i;
        float bb = bih[g] + bhh[g];
        float c0, c1, c2, c3;
        f2_unpack(acc2[i][0], c0, c1);
        f2_unpack(acc2[i][1], c2, c3);
        float4 o;
        o.x = c0 + bb; o.y = c1 + bb; o.z = c2 + bb; o.w = c3 + bb;
        size_t base = ((size_t)dir * G4 + g) * M_TOT + m0 + tx * 4;
        *(float4*)&g_xw[base] = o;
    }
}

// ---------------------------------------------------------------------------
// Kernel 2: cluster-local bidirectional LSTM recurrence. NO GLOBAL SYNC.
// Grid = 128 CTAs = 2 dirs x 8 batch-groups x 8 hidden-CTAs (cluster of 8).
// CTA owns 8 batch rows x 32 hidden units; thread (bb, jj) owns one cell and
// all 4 of its gates. W slice (128 rows x 256) lives in SMEM for all steps.
// h exchange: each thread PUSHES its h into all 8 cluster CTAs' next h
// buffer via mapa + st.shared::cluster (conflict-free: banks 4*bb+jj span
// all 32), then one HW cluster barrier (release/acquire built in).
// Double-buffered h; the per-step barrier orders step-s reads of buffer p
// before any step-s+1 push overwrites p.
// Warp layout (jj = tid>>3, bb = tid&7): W LDS.128 4-way shared, h LDS.128
// 8-way shared -> dot loop is fma-bound (~2048 cyc/step/SM).
// Dynamic SMEM: W_s[128][260] + h[2][8][260] = 149760 B (1 CTA/SM).
// ---------------------------------------------------------------------------
__global__ __launch_bounds__(256, 1) __cluster_dims__(CL_N, 1, 1)
void lstm_rec_kernel(
    const float* __restrict__ mask,
    const float* __restrict__ Whhf, const float* __restrict__ Whhb,
    float* __restrict__ out)
{
    extern __shared__ float smem[];
    float (*W_s)[RS] = (float(*)[RS])smem;          // 128 x 260
    float* hbuf = smem + WROWS * RS;                // [2][BB_N][RS]

    const int bid   = blockIdx.x;
    const int rank  = bid & (CL_N - 1);             // hidden-slice CTA in cluster
    const int cid   = bid >> 3;
    const int dir   = cid >> 3;
    const int group = cid & 7;                      // batch group
    const int j0    = rank * JJ_N;
    const float* __restrict__ Whh = dir ? Whhb : Whhf;

    const int tid = threadIdx.x;
    const int jj  = tid >> 3;                       // local hidden unit 0..31
    const int bb  = tid & 7;                        // local batch row 0..7
    const int bg  = group * BB_N + bb;              // global batch row

    // Load W slice: W_s[g*32+u][k] = Whh[g*HALFH + j0 + u][k]
    for (int idx = tid; idx < WROWS * (HALFH / 4); idx += 256) {
        int r = idx >> 6, kq = idx & 63;
        int g = r >> 5, u = r & 31;
        float4 w4 = *(const float4*)&Whh[(size_t)(g * HALFH + j0 + u) * HALFH + kq * 4];
        *(float4*)&W_s[r][kq * 4] = w4;
    }
    // Zero h buffer 0 (step-0 input)
    for (int idx = tid; idx < BB_N * (HALFH / 4); idx += 256) {
        int r = idx >> 6, kq = idx & 63;
        *(float4*)&hbuf[r * RS + kq * 4] = make_float4(0.f, 0.f, 0.f, 0.f);
    }
    float c = 0.0f;
    __syncthreads();   // local init done. No cluster sync needed: each CTA
                       // reads only its OWN buffers, and peers' first DSMEM
                       // pushes target buf1 (untouched by init).

    // Precompute remote addresses of this thread's h slot in each CTA's buf0.
    const u32 myslot = smem_u32(&hbuf[bb * RS + j0 + jj]);
    u32 raddr[CL_N];
#pragma unroll
    for (int t = 0; t < CL_N; t++) raddr[t] = mapa_u32(myslot, t);

    const float* __restrict__ Wp0 = &W_s[0 * JJ_N + jj][0];   // gate i row
    const float* __restrict__ Wp1 = &W_s[1 * JJ_N + jj][0];   // gate f row
    const float* __restrict__ Wp2 = &W_s[2 * JJ_N + jj][0];   // gate g row
    const float* __restrict__ Wp3 = &W_s[3 * JJ_N + jj][0];   // gate o row

    // Strength-reduced stream pointers (stride +/-B_SZ per step).
    const int t0 = dir ? (L_SEQ - 1) : 0;
    const ptrdiff_t dstep = dir ? -(ptrdiff_t)B_SZ : (ptrdiff_t)B_SZ;
    const float* __restrict__ xwd = g_xw + (size_t)dir * G4 * M_TOT;
    const float* pi = xwd + (size_t)(0 * HALFH + j0 + jj) * M_TOT + (size_t)t0 * B_SZ + bg;
    const float* pf = xwd + (size_t)(1 * HALFH + j0 + jj) * M_TOT + (size_t)t0 * B_SZ + bg;
    const float* pg = xwd + (size_t)(2 * HALFH + j0 + jj) * M_TOT + (size_t)t0 * B_SZ + bg;
    const float* po = xwd + (size_t)(3 * HALFH + j0 + jj) * M_TOT + (size_t)t0 * B_SZ + bg;
    const float* pm = mask + (size_t)t0 * B_SZ + bg;
    float* pout = out + ((size_t)t0 * B_SZ + bg) * 512 + dir * HALFH + j0 + jj;
    const ptrdiff_t dout = dstep * 512;

    int p = 0;

    for (int s = 0; s < L_SEQ; s++) {
        // Seed + mask loads issue early; consumed only AFTER the dot loop.
        float ai = __ldcs(pi), af = __ldcs(pf), ag = __ldcs(pg), ao = __ldcs(po);
        float mv = *pm;

        // Dot: gates[g](bb, j0+jj) = sum_k h[bb][k] * W_s[g*32+jj][k]
        const float* hr = hbuf + p * HBUF_FLOATS + bb * RS;
        u64 a0 = 0, a1 = 0, a2 = 0, a3 = 0;   // (even-k, odd-k) partial pairs
#pragma unroll 8
        for (int k = 0; k < HALFH; k += 4) {
            ulonglong2 hp = *(const ulonglong2*)&hr[k];
            ulonglong2 w0 = *(const ulonglong2*)&Wp0[k];
            ulonglong2 w1 = *(const ulonglong2*)&Wp1[k];
            ulonglong2 w2 = *(const ulonglong2*)&Wp2[k];
            ulonglong2 w3 = *(const ulonglong2*)&Wp3[k];
            a0 = f2_fma(hp.x, w0.x, a0);
            a0 = f2_fma(hp.y, w0.y, a0);
            a1 = f2_fma(hp.x, w1.x, a1);
            a1 = f2_fma(hp.y, w1.y, a1);
            a2 = f2_fma(hp.x, w2.x, a2);
            a2 = f2_fma(hp.y, w2.y, a2);
            a3 = f2_fma(hp.x, w3.x, a3);
            a3 = f2_fma(hp.y, w3.y, a3);
        }

        // Horizontal add + seeds; cell update (all local to this thread).
        float e0, o0, e1, o1, e2, o2, e3, o3;
        f2_unpack(a0, e0, o0);
        f2_unpack(a1, e1, o1);
        f2_unpack(a2, e2, o2);
        f2_unpack(a3, e3, o3);
        float gi = e0 + o0 + ai;
        float gf = e1 + o1 + af;
        float gg = e2 + o2 + ag;
        float go = e3 + o3 + ao;
        float si = 1.0f / (1.0f + __expf(-gi));
        float sf = 1.0f / (1.0f + __expf(-gf));
        float so = 1.0f / (1.0f + __expf(-go));
        c = sf * c + si * fast_tanh(gg);
        float h = so * fast_tanh(c);
        h *= mv;
        c *= mv;

        // Push h into every cluster CTA's NEXT buffer (incl. our own).
        const u32 off = (u32)((p ^ 1) * HBUF_BYTES);
#pragma unroll
        for (int t = 0; t < CL_N; t++)
            st_dsmem(raddr[t] + off, h);

        // Output store overlaps the barrier.
        *pout = h;

        // HW cluster barrier: release our DSMEM pushes, acquire peers'.
        cluster_sync_hw();

        p ^= 1;
        pi += dstep; pf += dstep; pg += dstep; po += dstep;
        pm += dstep; pout += dout;
    }
}

// ---------------------------------------------------------------------------
// Launch
// d_in: 0=x 1=mask 2=W_ih_f 3=W_hh_f 4=b_ih_f 5=b_hh_f 6=W_ih_b 7=W_hh_b 8=b_ih_b 9=b_hh_b
// ---------------------------------------------------------------------------
extern "C" void kernel_launch(void* const* d_in, const int* in_sizes, int n_in,
                              void* d_out, int out_size)
{
    const float* x     = (const float*)d_in[0];
    const float* mask  = (const float*)d_in[1];
    const float* Wihf  = (const float*)d_in[2];
    const float* Whhf  = (const float*)d_in[3];
    const float* bihf  = (const float*)d_in[4];
    const float* bhhf  = (const float*)d_in[5];
    const float* Wihb  = (const float*)d_in[6];
    const float* Whhb  = (const float*)d_in[7];
    const float* bihb  = (const float*)d_in[8];
    const float* bhhb  = (const float*)d_in[9];
    float* out = (float*)d_out;

    // Idempotent, deterministic; needed for 146 KB dynamic SMEM.
    cudaFuncSetAttribute(lstm_rec_kernel,
                         cudaFuncAttributeMaxDynamicSharedMemorySize, SMEM_BYTES);

    dim3 ggrid(M_TOT / 64, G4 / 64, 2);
    gemm_xw_kernel<<<ggrid, 256>>>(x, Wihf, Wihb, bihf, bhhf, bihb, bhhb);

    // 128 CTAs = 16 clusters of 8; batch groups independent -> no grid sync.
    lstm_rec_kernel<<<128, 256, SMEM_BYTES>>>(mask, Whhf, Whhb, out);
}

// round 17
// speedup vs baseline: 1.2006x; 1.2006x over previous
#include <cuda_runtime.h>
#include <cstddef>

#define L_SEQ 512
#define B_SZ  64
#define D_IN  512
#define HALFH 256
#define G4    1024                 // 4*HALF gate rows per direction
#define M_TOT (L_SEQ * B_SZ)      // 32768
#define NBPD  64                  // blocks per direction in recurrence
#define HB    4                   // hidden units per block
#define NSTG  (D_IN / 16)         // 32 k-stages in the GEMM

typedef unsigned long long u64;

// ---------------------------------------------------------------------------
// Packed fp32x2 helpers (sm_100+). IEEE fp32 per lane -> bit-identical math.
// ---------------------------------------------------------------------------
__device__ __forceinline__ u64 f2_dup(float v) {
    u64 r; asm("mov.b64 %0, {%1, %1};" : "=l"(r) : "f"(v)); return r;
}
__device__ __forceinline__ void f2_unpack(u64 p, float& lo, float& hi) {
    asm("mov.b64 {%0, %1}, %2;" : "=f"(lo), "=f"(hi) : "l"(p));
}
__device__ __forceinline__ u64 f2_fma(u64 a, u64 b, u64 c) {
    u64 d; asm("fma.rn.f32x2 %0, %1, %2, %3;" : "=l"(d) : "l"(a), "l"(b), "l"(c));
    return d;
}

// Morally-strong gpu-scope acquire/release on u32 (bypass L1, no IVALL).
__device__ __forceinline__ unsigned ld_acq(const unsigned* p) {
    unsigned v;
    asm volatile("ld.acquire.gpu.global.u32 %0, [%1];" : "=r"(v) : "l"(p) : "memory");
    return v;
}
__device__ __forceinline__ void st_rel(unsigned* p, unsigned v) {
    asm volatile("st.release.gpu.global.u32 [%0], %1;" :: "l"(p), "r"(v) : "memory");
}

// Scratch: xw[dir][g][m] with m = l*B + b   (256 MB, module-static: allowed)
__device__ float g_xw[(size_t)2 * G4 * M_TOT];
// Double-buffered hidden state: [dir][buf][b][k]
__device__ float g_h[2][2][B_SZ][HALFH];
// Flag barrier state: per-block flags (32B stride, no contention) + gen word.
__device__ unsigned g_flag[2][NBPD * 8];
__device__ unsigned g_gen[2][32];          // [dir][0], padded to separate lines

// ---------------------------------------------------------------------------
// Kernel 1 (v2): xw[dir][g][m] = sum_d W_ih[g][d]*x[m][d] + b_ih[g] + b_hh[g]
// 64(g) x 64(m) x 16(k) tiles, 256 threads, 4x4 register tile, FFMA2 math.
// DOUBLE-BUFFERED smem stages with register prefetch: ONE bar.sync per stage
// (32 total vs 64) and LDG latency fully overlapped with the compute stage.
// ---------------------------------------------------------------------------
__global__ __launch_bounds__(256) void gemm_xw_kernel(
    const float* __restrict__ x,
    const float* __restrict__ Wf, const float* __restrict__ Wb,
    const float* __restrict__ bihf, const float* __restrict__ bhhf,
    const float* __restrict__ bihb, const float* __restrict__ bhhb)
{
    const int dir = blockIdx.z;
    const float* __restrict__ W   = dir ? Wb   : Wf;
    const float* __restrict__ bih = dir ? bihb : bihf;
    const float* __restrict__ bhh = dir ? bhhb : bhhf;

    const int m0 = blockIdx.x * 64;
    const int g0 = blockIdx.y * 64;

    __shared__ float As[2][16][68];   // As[buf][k][g']
    __shared__ float Bs[2][16][68];   // Bs[buf][k][m']

    const int tid = threadIdx.x;
    const int tx  = tid & 15;      // m sub-tile
    const int ty  = tid >> 4;      // g sub-tile

    const int lrow = tid >> 2;          // 0..63 (tile row to load)
    const int lc   = (tid & 3) * 4;     // k offset 0,4,8,12

    const float* Arow = W + (size_t)(g0 + lrow) * D_IN + lc;
    const float* Brow = x + (size_t)(m0 + lrow) * D_IN + lc;

    // Preload: stage 0 -> smem[0]; stage 1 -> regs.
    {
        float4 a0 = *(const float4*)(Arow);
        float4 b0 = *(const float4*)(Brow);
        As[0][lc + 0][lrow] = a0.x; As[0][lc + 1][lrow] = a0.y;
        As[0][lc + 2][lrow] = a0.z; As[0][lc + 3][lrow] = a0.w;
        Bs[0][lc + 0][lrow] = b0.x; Bs[0][lc + 1][lrow] = b0.y;
        Bs[0][lc + 2][lrow] = b0.z; Bs[0][lc + 3][lrow] = b0.w;
    }
    float4 avn = *(const float4*)(Arow + 16);
    float4 bvn = *(const float4*)(Brow + 16);
    __syncthreads();

    u64 acc2[4][2] = {};

    for (int s = 0; s < NSTG; s++) {
        const int cur = s & 1;
        // Stage s+1: regs -> smem[cur^1] (read in iter s+1, after the sync).
        if (s + 1 < NSTG) {
            As[cur ^ 1][lc + 0][lrow] = avn.x; As[cur ^ 1][lc + 1][lrow] = avn.y;
            As[cur ^ 1][lc + 2][lrow] = avn.z; As[cur ^ 1][lc + 3][lrow] = avn.w;
            Bs[cur ^ 1][lc + 0][lrow] = bvn.x; Bs[cur ^ 1][lc + 1][lrow] = bvn.y;
            Bs[cur ^ 1][lc + 2][lrow] = bvn.z; Bs[cur ^ 1][lc + 3][lrow] = bvn.w;
        }
        // Prefetch stage s+2 into regs (overlaps the compute below).
        if (s + 2 < NSTG) {
            avn = *(const float4*)(Arow + (s + 2) * 16);
            bvn = *(const float4*)(Brow + (s + 2) * 16);
        }
#pragma unroll
        for (int kk = 0; kk < 16; kk++) {
            float4     a  = *(const float4*)&As[cur][kk][ty * 4];
            ulonglong2 bp = *(const ulonglong2*)&Bs[cur][kk][tx * 4];
            u64 d0 = f2_dup(a.x), d1 = f2_dup(a.y),
                d2 = f2_dup(a.z), d3 = f2_dup(a.w);
            acc2[0][0] = f2_fma(d0, bp.x, acc2[0][0]);
            acc2[0][1] = f2_fma(d0, bp.y, acc2[0][1]);
            acc2[1][0] = f2_fma(d1, bp.x, acc2[1][0]);
            acc2[1][1] = f2_fma(d1, bp.y, acc2[1][1]);
            acc2[2][0] = f2_fma(d2, bp.x, acc2[2][0]);
            acc2[2][1] = f2_fma(d2, bp.y, acc2[2][1]);
            acc2[3][0] = f2_fma(d3, bp.x, acc2[3][0]);
            acc2[3][1] = f2_fma(d3, bp.y, acc2[3][1]);
        }
        __syncthreads();   // one sync per stage
    }

#pragma unroll
    for (int i = 0; i < 4; i++) {
        int g = g0 + ty * 4 + i;
        float bb = bih[g] + bhh[g];
        float c0, c1, c2, c3;
        f2_unpack(acc2[i][0], c0, c1);
        f2_unpack(acc2[i][1], c2, c3);
        float4 o;
        o.x = c0 + bb; o.y = c1 + bb; o.z = c2 + bb; o.w = c3 + bb;
        size_t base = ((size_t)dir * G4 + g) * M_TOT + m0 + tx * 4;
        *(float4*)&g_xw[base] = o;
    }
}

// ---------------------------------------------------------------------------
// Contention-free 2-HOP flag barrier (EXACT best-measured R8 protocol).
// Arrival: one st.release.gpu to a per-block 32B-padded flag. Leader block
// gathers the 64 flags (one thread each), bar.sync, releases gen; others
// spin gen with a single thread (one shared read line, low contention).
// ---------------------------------------------------------------------------
__device__ __forceinline__ void flag_barrier(int dir, int blk_local,
                                             unsigned target, int tid)
{
    __syncthreads();
    if (tid == 0)
        st_rel(&g_flag[dir][blk_local * 8], target);
    if (blk_local == 0) {
        if (tid < NBPD) {
            unsigned v;
            do { v = ld_acq(&g_flag[dir][tid * 8]); }
            while ((int)(v - target) < 0);
        }
        __syncthreads();
        if (tid == 0)
            st_rel(&g_gen[dir][0], target);
    } else {
        if (tid == 0) {
            unsigned v;
            do { v = ld_acq(&g_gen[dir][0]); }
            while ((int)(v - target) < 0);
        }
        __syncthreads();
    }
}

// ---------------------------------------------------------------------------
// Kernel 2: persistent bidirectional LSTM recurrence.
// EXACT copy of the best-measured configuration (5106.5 us).
// ---------------------------------------------------------------------------
__global__ __launch_bounds__(256, 1) void lstm_rec_kernel(
    const float* __restrict__ mask,
    const float* __restrict__ Whhf, const float* __restrict__ Whhb,
    float* __restrict__ out)
{
    extern __shared__ float smem[];
    float (*h_s)[260] = (float(*)[260])smem;                     // 64 x 260
    float (*W_p)[520] = (float(*)[520])(smem + 64 * 260);        // 8  x 520

    const int blk = blockIdx.x;
    const int dir = blk >> 6;
    const int blk_local = blk & 63;
    const int j0  = blk_local * HB;
    const float* __restrict__ Whh = dir ? Whhb : Whhf;

    const int tid = threadIdx.x;
    const int b   = tid & 63;     // batch lane
    const int q   = tid >> 6;     // local hidden unit owned by this thread

    // Monotonic barrier base from previous launch (all threads read same).
    const unsigned base = ld_acq(&g_gen[dir][0]);

    // Load W slice pair-interleaved BY HIDDEN UNIT:
    //   local row r = jj*4 + gt  <-  Whh[gt*HALF + j0 + jj][:]
    //   pair pr = jj*2 + (gt>>1), slot = gt&1;  W_p[pr][2*k + slot] = row[k]
    for (int idx = tid; idx < 16 * 64; idx += 256) {
        int r = idx >> 6, kq = idx & 63;
        int jj = r >> 2, gt = r & 3;
        float4 w4 = *(const float4*)&Whh[(size_t)(gt * HALFH + j0 + jj) * HALFH + kq * 4];
        int pr = jj * 2 + (gt >> 1), slot = gt & 1, kb = kq * 4;
        W_p[pr][2 * (kb + 0) + slot] = w4.x;
        W_p[pr][2 * (kb + 1) + slot] = w4.y;
        W_p[pr][2 * (kb + 2) + slot] = w4.z;
        W_p[pr][2 * (kb + 3) + slot] = w4.w;
    }

    // Zero our slice of the step-0 read buffer; c lives in a register.
    g_h[dir][0][b][j0 + q] = 0.0f;
    float c = 0.0f;

    flag_barrier(dir, blk_local, base + 1, tid);   // zeros visible to all

    const float* __restrict__ WpIF = &W_p[2 * q + 0][0];   // gates (i,f)
    const float* __restrict__ WpGO = &W_p[2 * q + 1][0];   // gates (g,o)

    // Strength-reduced stream pointers (stride +/-B_SZ per step).
    const int t0 = dir ? (L_SEQ - 1) : 0;
    const ptrdiff_t dstep = dir ? -(ptrdiff_t)B_SZ : (ptrdiff_t)B_SZ;
    const float* __restrict__ xwb =
        g_xw + (size_t)dir * G4 * M_TOT + (size_t)t0 * B_SZ + b;
    const float* pi = xwb + (size_t)(0 * HALFH + j0 + q) * M_TOT;
    const float* pf = xwb + (size_t)(1 * HALFH + j0 + q) * M_TOT;
    const float* pg = xwb + (size_t)(2 * HALFH + j0 + q) * M_TOT;
    const float* po = xwb + (size_t)(3 * HALFH + j0 + q) * M_TOT;
    const float* pm = mask + (size_t)t0 * B_SZ + b;
    float* pout = out + ((size_t)t0 * B_SZ + b) * 512 + dir * HALFH + j0 + q;
    const ptrdiff_t dout = dstep * 512;

    // Staging: thread covers rows bb = (tid>>6) + {0,4,...,60} at column
    // block kq = (tid & 63)*4; 16 front-batched LDG.128 then 16 STS.128.
    const int st_b0 = tid >> 6;          // 0..3
    const int st_kq = (tid & 63) * 4;    // 0..252
    const float* hsrc0 = &g_h[dir][0][0][0] + (size_t)st_b0 * HALFH + st_kq;
    const size_t hbufoff = (size_t)B_SZ * HALFH;   // floats between buf0/buf1
    float* hdst1 = &g_h[dir][1][0][0] + (size_t)b * HALFH + j0 + q;
    float* hwr[2] = { hdst1 - hbufoff, hdst1 };    // write ptr per target buf

    int rbuf = 0;

    for (int s = 0; s < L_SEQ; s++) {
        // Seed + mask loads issue early; consumed only AFTER the dot loop.
        float ai = __ldcs(pi), af = __ldcs(pf), ag = __ldcs(pg), ao = __ldcs(po);
        float mv = *pm;

        // Stage full h (64x256) from L2 (ldcg: coherent, bypasses stale L1).
        {
            const float* src = hsrc0 + (size_t)rbuf * hbufoff;
            float4 r[16];
#pragma unroll
            for (int i = 0; i < 16; i++)
                r[i] = __ldcg((const float4*)(src + (size_t)(i * 4) * HALFH));
#pragma unroll
            for (int i = 0; i < 16; i++)
                *(float4*)&h_s[st_b0 + i * 4][st_kq] = r[i];
        }
        __syncthreads();

        u64 accIF = 0;   // packed (0.0f, 0.0f)
        u64 accGO = 0;

        // gates(i,f,g,o)[b, j0+q] += sum_k h[b][k] * W[row][k]
#pragma unroll 8
        for (int k = 0; k < HALFH; k += 4) {
            float4 h4 = *(const float4*)&h_s[b][k];
            ulonglong2 wi0 = *(const ulonglong2*)&WpIF[2 * k];     // k, k+1
            ulonglong2 wi1 = *(const ulonglong2*)&WpIF[2 * k + 4]; // k+2, k+3
            ulonglong2 wg0 = *(const ulonglong2*)&WpGO[2 * k];
            ulonglong2 wg1 = *(const ulonglong2*)&WpGO[2 * k + 4];
            u64 hx = f2_dup(h4.x), hy = f2_dup(h4.y),
                hz = f2_dup(h4.z), hw = f2_dup(h4.w);
            accIF = f2_fma(hx, wi0.x, accIF);
            accIF = f2_fma(hy, wi0.y, accIF);
            accIF = f2_fma(hz, wi1.x, accIF);
            accIF = f2_fma(hw, wi1.y, accIF);
            accGO = f2_fma(hx, wg0.x, accGO);
            accGO = f2_fma(hy, wg0.y, accGO);
            accGO = f2_fma(hz, wg1.x, accGO);
            accGO = f2_fma(hw, wg1.y, accGO);
        }

        // Cell update: add seeds now (their latency is long hidden).
        float di, df, dg, dgo;
        f2_unpack(accIF, di, df);
        f2_unpack(accGO, dg, dgo);
        float gi = di + ai, gf = df + af, gg = dg + ag, go = dgo + ao;
        float si = 1.0f / (1.0f + __expf(-gi));
        float sf = 1.0f / (1.0f + __expf(-gf));
        float so = 1.0f / (1.0f + __expf(-go));
        c = sf * c + si * tanhf(gg);
        float h = so * tanhf(c);
        h *= mv;
        c *= mv;

        hwr[rbuf ^ 1][0] = h;   // write h to the other buffer (plain STG -> L2)
        *pout = h;

        flag_barrier(dir, blk_local, base + 2 + s, tid);  // all blocks step

        rbuf ^= 1;
        pi += dstep; pf += dstep; pg += dstep; po += dstep;
        pm += dstep; pout += dout;
    }
}

// ---------------------------------------------------------------------------
// Launch
// d_in: 0=x 1=mask 2=W_ih_f 3=W_hh_f 4=b_ih_f 5=b_hh_f 6=W_ih_b 7=W_hh_b 8=b_ih_b 9=b_hh_b
// ---------------------------------------------------------------------------
extern "C" void kernel_launch(void* const* d_in, const int* in_sizes, int n_in,
                              void* d_out, int out_size)
{
    const float* x     = (const float*)d_in[0];
    const float* mask  = (const float*)d_in[1];
    const float* Wihf  = (const float*)d_in[2];
    const float* Whhf  = (const float*)d_in[3];
    const float* bihf  = (const float*)d_in[4];
    const float* bhhf  = (const float*)d_in[5];
    const float* Wihb  = (const float*)d_in[6];
    const float* Whhb  = (const float*)d_in[7];
    const float* bihb  = (const float*)d_in[8];
    const float* bhhb  = (const float*)d_in[9];
    float* out = (float*)d_out;

    // Idempotent, deterministic; needed for 83 KB dynamic SMEM.
    cudaFuncSetAttribute(lstm_rec_kernel,
                         cudaFuncAttributeMaxDynamicSharedMemorySize, 83200);

    dim3 ggrid(M_TOT / 64, G4 / 64, 2);
    gemm_xw_kernel<<<ggrid, 256>>>(x, Wihf, Wihb, bihf, bhhf, bihb, bhhb);

    lstm_rec_kernel<<<2 * NBPD, 256, 83200>>>(mask, Whhf, Whhb, out);
}